// round 2
// baseline (speedup 1.0000x reference)
#include <cuda_runtime.h>
#include <cuda_bf16.h>
#include <math.h>

#define NN 50000
#define NE 800000
#define IN_C 128
#define HID 32
#define HEADS 8
#define H1C (HEADS*HID)   // 256
#define OUT_C 64
#define NEG_SLOPE 0.2f
#define EPS_F 1e-16f

__device__ float g_h1[(size_t)NN * H1C];
__device__ float g_out1[(size_t)NN * H1C];
__device__ float g_h2[(size_t)NN * OUT_C];
__device__ float g_asrc1[NN * HEADS];
__device__ float g_adst1[NN * HEADS];
__device__ float g_m1[NN * HEADS];
__device__ float g_den1[NN * HEADS];
__device__ float g_asrc2[NN];
__device__ float g_adst2[NN];
__device__ float g_m2[NN];
__device__ float g_den2[NN];

__device__ __forceinline__ void redAdd4(float* p, float a, float b, float c, float d) {
    asm volatile("red.global.add.v4.f32 [%0], {%1,%2,%3,%4};"
                 :: "l"(p), "f"(a), "f"(b), "f"(c), "f"(d) : "memory");
}
__device__ __forceinline__ void redAdd2(float* p, float a, float b) {
    asm volatile("red.global.add.v2.f32 [%0], {%1,%2};"
                 :: "l"(p), "f"(a), "f"(b) : "memory");
}
__device__ __forceinline__ void atomicMaxFloat(float* addr, float v) {
    if (v >= 0.0f) atomicMax((int*)addr, __float_as_int(v));
    else           atomicMin((unsigned int*)addr, __float_as_uint(v));
}
__device__ __forceinline__ float lrelu(float x) { return x >= 0.0f ? x : NEG_SLOPE * x; }

__global__ void fill_kernel(float* __restrict__ p, int n, float v) {
    int i = blockIdx.x * blockDim.x + threadIdx.x;
    if (i < n) p[i] = v;
}

__global__ __launch_bounds__(256) void sgemm64(const float* __restrict__ A,
                                               const float* __restrict__ B,
                                               float* __restrict__ C,
                                               int M, int N, int K) {
    __shared__ float As[16][64];
    __shared__ float Bs[16][64];
    int t  = threadIdx.x;
    int tx = t & 15, ty = t >> 4;
    int bR = blockIdx.y, bC = blockIdx.x;

    float acc[4][4];
    #pragma unroll
    for (int i = 0; i < 4; i++)
        #pragma unroll
        for (int j = 0; j < 4; j++) acc[i][j] = 0.0f;

    int aRow = t >> 2, aCol = (t & 3) * 4;
    int bRow = t >> 4, bCol = (t & 15) * 4;
    int gRowA = bR * 64 + aRow;

    for (int k0 = 0; k0 < K; k0 += 16) {
        float4 av = make_float4(0.f, 0.f, 0.f, 0.f);
        if (gRowA < M) av = *(const float4*)(A + (size_t)gRowA * K + k0 + aCol);
        As[aCol + 0][aRow] = av.x;
        As[aCol + 1][aRow] = av.y;
        As[aCol + 2][aRow] = av.z;
        As[aCol + 3][aRow] = av.w;
        *(float4*)&Bs[bRow][bCol] =
            *(const float4*)(B + (size_t)(k0 + bRow) * N + bC * 64 + bCol);
        __syncthreads();
        #pragma unroll
        for (int kk = 0; kk < 16; kk++) {
            float4 a4 = *(float4*)&As[kk][ty * 4];
            float4 b4 = *(float4*)&Bs[kk][tx * 4];
            float ar[4] = {a4.x, a4.y, a4.z, a4.w};
            float br[4] = {b4.x, b4.y, b4.z, b4.w};
            #pragma unroll
            for (int i = 0; i < 4; i++)
                #pragma unroll
                for (int j = 0; j < 4; j++) acc[i][j] += ar[i] * br[j];
        }
        __syncthreads();
    }
    #pragma unroll
    for (int i = 0; i < 4; i++) {
        int row = bR * 64 + ty * 4 + i;
        if (row < M) {
            float4 o = make_float4(acc[i][0], acc[i][1], acc[i][2], acc[i][3]);
            *(float4*)(C + (size_t)row * N + bC * 64 + tx * 4) = o;
        }
    }
}

__global__ void att_kernel(const float* __restrict__ h,
                           const float* __restrict__ att_src,
                           const float* __restrict__ att_dst,
                           float* __restrict__ asrc, float* __restrict__ adst,
                           int N, int H, int C) {
    int warp = (blockIdx.x * blockDim.x + threadIdx.x) >> 5;
    int lane = threadIdx.x & 31;
    if (warp >= N * H) return;
    int hh = warp % H;
    const float* hp = h + (size_t)warp * C;
    float ss = 0.f, sd = 0.f;
    for (int c = lane; c < C; c += 32) {
        float v = hp[c];
        ss += v * att_src[hh * C + c];
        sd += v * att_dst[hh * C + c];
    }
    #pragma unroll
    for (int o = 16; o; o >>= 1) {
        ss += __shfl_down_sync(0xffffffffu, ss, o);
        sd += __shfl_down_sync(0xffffffffu, sd, o);
    }
    if (lane == 0) { asrc[warp] = ss; adst[warp] = sd; }
}

__global__ void edge_max1(const int* __restrict__ ei, int E) {
    int e = blockIdx.x * blockDim.x + threadIdx.x;
    if (e >= E) return;
    int s = ei[e], d = ei[E + e];
    const float4* as = (const float4*)(g_asrc1 + (size_t)s * 8);
    const float4* ad = (const float4*)(g_adst1 + (size_t)d * 8);
    float4 a0 = as[0], a1 = as[1], b0 = ad[0], b1 = ad[1];
    float ev[8] = {lrelu(a0.x + b0.x), lrelu(a0.y + b0.y), lrelu(a0.z + b0.z), lrelu(a0.w + b0.w),
                   lrelu(a1.x + b1.x), lrelu(a1.y + b1.y), lrelu(a1.z + b1.z), lrelu(a1.w + b1.w)};
    float* mp = g_m1 + (size_t)d * 8;
    #pragma unroll
    for (int h = 0; h < 8; h++) atomicMaxFloat(mp + h, ev[h]);
}

__global__ void edge_sum1(const int* __restrict__ ei, int E) {
    int e = blockIdx.x * blockDim.x + threadIdx.x;
    if (e >= E) return;
    int s = ei[e], d = ei[E + e];
    const float4* as = (const float4*)(g_asrc1 + (size_t)s * 8);
    const float4* ad = (const float4*)(g_adst1 + (size_t)d * 8);
    const float4* mp = (const float4*)(g_m1 + (size_t)d * 8);
    float4 a0 = as[0], a1 = as[1], b0 = ad[0], b1 = ad[1];
    float4 m0 = mp[0], m1v = mp[1];
    float e0 = __expf(lrelu(a0.x + b0.x) - m0.x);
    float e1 = __expf(lrelu(a0.y + b0.y) - m0.y);
    float e2 = __expf(lrelu(a0.z + b0.z) - m0.z);
    float e3 = __expf(lrelu(a0.w + b0.w) - m0.w);
    float e4 = __expf(lrelu(a1.x + b1.x) - m1v.x);
    float e5 = __expf(lrelu(a1.y + b1.y) - m1v.y);
    float e6 = __expf(lrelu(a1.z + b1.z) - m1v.z);
    float e7 = __expf(lrelu(a1.w + b1.w) - m1v.w);
    float* dp = g_den1 + (size_t)d * 8;
    redAdd4(dp, e0, e1, e2, e3);
    redAdd4(dp + 4, e4, e5, e6, e7);
}

__global__ __launch_bounds__(256) void edge_agg1(const int* __restrict__ ei, int E) {
    int warp = (blockIdx.x * blockDim.x + threadIdx.x) >> 5;
    if (warp >= E) return;
    int lane = threadIdx.x & 31;
    int s = ei[warp], d = ei[E + warp];
    int h = lane >> 2;
    float e  = lrelu(g_asrc1[s * 8 + h] + g_adst1[d * 8 + h]);
    float m  = g_m1[d * 8 + h];
    float dn = g_den1[d * 8 + h];
    float alpha = __expf(e - m) / (dn + EPS_F);
    const float* hs = g_h1 + (size_t)s * H1C + lane * 8;
    float* po       = g_out1 + (size_t)d * H1C + lane * 8;
    float4 v0 = *(const float4*)hs;
    float4 v1 = *(const float4*)(hs + 4);
    redAdd4(po,     v0.x * alpha, v0.y * alpha, v0.z * alpha, v0.w * alpha);
    redAdd4(po + 4, v1.x * alpha, v1.y * alpha, v1.z * alpha, v1.w * alpha);
}

__global__ void elu_bias_kernel(const float* __restrict__ bias, int n) {
    int i = blockIdx.x * blockDim.x + threadIdx.x;
    if (i >= n) return;
    float v = g_out1[i] + bias[i & (H1C - 1)];
    g_out1[i] = v > 0.0f ? v : expm1f(v);
}

__global__ void edge_max2(const int* __restrict__ ei, int E) {
    int e = blockIdx.x * blockDim.x + threadIdx.x;
    if (e >= E) return;
    int s = ei[e], d = ei[E + e];
    float ev = lrelu(g_asrc2[s] + g_adst2[d]);
    atomicMaxFloat(g_m2 + d, ev);
}
__global__ void edge_sum2(const int* __restrict__ ei, int E) {
    int e = blockIdx.x * blockDim.x + threadIdx.x;
    if (e >= E) return;
    int s = ei[e], d = ei[E + e];
    float ev = lrelu(g_asrc2[s] + g_adst2[d]);
    atomicAdd(g_den2 + d, __expf(ev - g_m2[d]));
}
__global__ __launch_bounds__(256) void edge_agg2(const int* __restrict__ ei, int E,
                                                 float* __restrict__ out) {
    int warp = (blockIdx.x * blockDim.x + threadIdx.x) >> 5;
    if (warp >= E) return;
    int lane = threadIdx.x & 31;
    int s = ei[warp], d = ei[E + warp];
    float e  = lrelu(g_asrc2[s] + g_adst2[d]);
    float alpha = __expf(e - g_m2[d]) / (g_den2[d] + EPS_F);
    const float* hs = g_h2 + (size_t)s * OUT_C + lane * 2;
    float* po       = out + (size_t)d * OUT_C + lane * 2;
    redAdd2(po, hs[0] * alpha, hs[1] * alpha);
}

__global__ void bias2_kernel(float* __restrict__ out, const float* __restrict__ bias, int n) {
    int i = blockIdx.x * blockDim.x + threadIdx.x;
    if (i >= n) return;
    out[i] += bias[i & (OUT_C - 1)];
}

extern "C" void kernel_launch(void* const* d_in, const int* in_sizes, int n_in,
                              void* d_out, int out_size) {
    const float* x        = (const float*)d_in[0];
    const int*   ei       = (const int*)d_in[1];     // int32 (JAX x64 disabled)
    const float* W1       = (const float*)d_in[2];
    const float* att_src1 = (const float*)d_in[3];
    const float* att_dst1 = (const float*)d_in[4];
    const float* bias1    = (const float*)d_in[5];
    const float* W2       = (const float*)d_in[6];
    const float* att_src2 = (const float*)d_in[7];
    const float* att_dst2 = (const float*)d_in[8];
    const float* bias2    = (const float*)d_in[9];
    float* out = (float*)d_out;

    const int N = in_sizes[0] / IN_C;
    const int E = in_sizes[1] / 2;

    float *p_out1, *p_m1, *p_den1, *p_m2, *p_den2, *p_h1, *p_h2;
    float *p_as1, *p_ad1, *p_as2, *p_ad2;
    cudaGetSymbolAddress((void**)&p_out1, g_out1);
    cudaGetSymbolAddress((void**)&p_m1,   g_m1);
    cudaGetSymbolAddress((void**)&p_den1, g_den1);
    cudaGetSymbolAddress((void**)&p_m2,   g_m2);
    cudaGetSymbolAddress((void**)&p_den2, g_den2);
    cudaGetSymbolAddress((void**)&p_h1,   g_h1);
    cudaGetSymbolAddress((void**)&p_h2,   g_h2);
    cudaGetSymbolAddress((void**)&p_as1,  g_asrc1);
    cudaGetSymbolAddress((void**)&p_ad1,  g_adst1);
    cudaGetSymbolAddress((void**)&p_as2,  g_asrc2);
    cudaGetSymbolAddress((void**)&p_ad2,  g_adst2);

    const float NEG_INF = -__builtin_huge_valf();
    const int T = 256;

    fill_kernel<<<(N * H1C + T - 1) / T, T>>>(p_out1, N * H1C, 0.0f);
    fill_kernel<<<(N * HEADS + T - 1) / T, T>>>(p_m1, N * HEADS, NEG_INF);
    fill_kernel<<<(N * HEADS + T - 1) / T, T>>>(p_den1, N * HEADS, 0.0f);
    fill_kernel<<<(N + T - 1) / T, T>>>(p_m2, N, NEG_INF);
    fill_kernel<<<(N + T - 1) / T, T>>>(p_den2, N, 0.0f);
    fill_kernel<<<(N * OUT_C + T - 1) / T, T>>>(out, N * OUT_C, 0.0f);

    {
        dim3 grid(H1C / 64, (N + 63) / 64);
        sgemm64<<<grid, 256>>>(x, W1, p_h1, N, H1C, IN_C);
    }
    att_kernel<<<(N * HEADS * 32 + T - 1) / T, T>>>(p_h1, att_src1, att_dst1,
                                                    p_as1, p_ad1, N, HEADS, HID);
    edge_max1<<<(E + T - 1) / T, T>>>(ei, E);
    edge_sum1<<<(E + T - 1) / T, T>>>(ei, E);
    edge_agg1<<<(int)(((size_t)E * 32 + T - 1) / T), T>>>(ei, E);
    elu_bias_kernel<<<(N * H1C + T - 1) / T, T>>>(bias1, N * H1C);

    {
        dim3 grid(OUT_C / 64, (N + 63) / 64);
        sgemm64<<<grid, 256>>>(p_out1, W2, p_h2, N, OUT_C, H1C);
    }
    att_kernel<<<(N * 32 + T - 1) / T, T>>>(p_h2, att_src2, att_dst2,
                                            p_as2, p_ad2, N, 1, OUT_C);
    edge_max2<<<(E + T - 1) / T, T>>>(ei, E);
    edge_sum2<<<(E + T - 1) / T, T>>>(ei, E);
    edge_agg2<<<(int)(((size_t)E * 32 + T - 1) / T), T>>>(ei, E, out);
    bias2_kernel<<<(N * OUT_C + T - 1) / T, T>>>(out, bias2, N * OUT_C);
}

// round 3
// speedup vs baseline: 1.0672x; 1.0672x over previous
#include <cuda_runtime.h>
#include <cuda_bf16.h>
#include <math.h>

#define NN 50000
#define NE 800000
#define IN_C 128
#define HID 32
#define HEADS 8
#define H1C (HEADS*HID)   // 256
#define OUT_C 64
#define NEG_SLOPE 0.2f
#define EPS_F 1e-16f

__device__ float g_h1[(size_t)NN * H1C];
__device__ float g_out1[(size_t)NN * H1C];
__device__ float g_h2[(size_t)NN * OUT_C];
__device__ float g_e1[(size_t)NE * HEADS];   // per-edge scores; reused as ee; layer2 aliases head
__device__ float g_asrc1[NN * HEADS];
__device__ float g_adst1[NN * HEADS];
__device__ float g_m1[NN * HEADS];
__device__ float g_den1[NN * HEADS];
__device__ float g_asrc2[NN];
__device__ float g_adst2[NN];
__device__ float g_m2[NN];
__device__ float g_den2[NN];

__device__ __forceinline__ void redAdd4(float* p, float a, float b, float c, float d) {
    asm volatile("red.global.add.v4.f32 [%0], {%1,%2,%3,%4};"
                 :: "l"(p), "f"(a), "f"(b), "f"(c), "f"(d) : "memory");
}
__device__ __forceinline__ void redAdd2(float* p, float a, float b) {
    asm volatile("red.global.add.v2.f32 [%0], {%1,%2};"
                 :: "l"(p), "f"(a), "f"(b) : "memory");
}
__device__ __forceinline__ void atomicMaxFloat(float* addr, float v) {
    if (v >= 0.0f) atomicMax((int*)addr, __float_as_int(v));
    else           atomicMin((unsigned int*)addr, __float_as_uint(v));
}
__device__ __forceinline__ float lrelu(float x) { return x >= 0.0f ? x : NEG_SLOPE * x; }

__global__ void fill_kernel(float* __restrict__ p, int n, float v) {
    int i = blockIdx.x * blockDim.x + threadIdx.x;
    if (i < n) p[i] = v;
}

// C[M,N] = A[M,K] @ B[K,N].  BM=128, BN=64, BK=16, 256 thr, 8x4 micro.
// Requires: N % 64 == 0, K % 16 == 0 (true: N in {256,64}, K in {128,256}).
__global__ __launch_bounds__(256) void sgemm128x64(const float* __restrict__ A,
                                                   const float* __restrict__ B,
                                                   float* __restrict__ C,
                                                   int M, int N, int K) {
    __shared__ float As[16][128];
    __shared__ float Bs[16][64];
    int t  = threadIdx.x;
    int tx = t & 15, ty = t >> 4;         // tx: 16 col-groups of 4, ty: 16 row-groups of 8
    int bR = blockIdx.y, bC = blockIdx.x;

    float acc[8][4];
    #pragma unroll
    for (int i = 0; i < 8; i++)
        #pragma unroll
        for (int j = 0; j < 4; j++) acc[i][j] = 0.0f;

    // A tile load: thread t loads row (t>>1), cols (t&1)*8 .. +7 (2 float4)
    int aRow = t >> 1;
    int aCol = (t & 1) * 8;
    int gRowA = bR * 128 + aRow;
    // B tile load: thread t loads row (t>>4), cols (t&15)*4 (1 float4)
    int bRow = t >> 4;
    int bCol = (t & 15) * 4;

    for (int k0 = 0; k0 < K; k0 += 16) {
        float4 a0 = make_float4(0.f,0.f,0.f,0.f), a1 = a0;
        if (gRowA < M) {
            const float* ap = A + (size_t)gRowA * K + k0 + aCol;
            a0 = *(const float4*)ap;
            a1 = *(const float4*)(ap + 4);
        }
        As[aCol + 0][aRow] = a0.x; As[aCol + 1][aRow] = a0.y;
        As[aCol + 2][aRow] = a0.z; As[aCol + 3][aRow] = a0.w;
        As[aCol + 4][aRow] = a1.x; As[aCol + 5][aRow] = a1.y;
        As[aCol + 6][aRow] = a1.z; As[aCol + 7][aRow] = a1.w;
        *(float4*)&Bs[bRow][bCol] =
            *(const float4*)(B + (size_t)(k0 + bRow) * N + bC * 64 + bCol);
        __syncthreads();
        #pragma unroll
        for (int kk = 0; kk < 16; kk++) {
            float4 b4 = *(float4*)&Bs[kk][tx * 4];
            float4 a40 = *(float4*)&As[kk][ty * 8];
            float4 a41 = *(float4*)&As[kk][ty * 8 + 4];
            float ar[8] = {a40.x, a40.y, a40.z, a40.w, a41.x, a41.y, a41.z, a41.w};
            float br[4] = {b4.x, b4.y, b4.z, b4.w};
            #pragma unroll
            for (int i = 0; i < 8; i++)
                #pragma unroll
                for (int j = 0; j < 4; j++) acc[i][j] += ar[i] * br[j];
        }
        __syncthreads();
    }
    #pragma unroll
    for (int i = 0; i < 8; i++) {
        int row = bR * 128 + ty * 8 + i;
        if (row < M) {
            float4 o = make_float4(acc[i][0], acc[i][1], acc[i][2], acc[i][3]);
            *(float4*)(C + (size_t)row * N + bC * 64 + tx * 4) = o;
        }
    }
}

__global__ void att_kernel(const float* __restrict__ h,
                           const float* __restrict__ att_src,
                           const float* __restrict__ att_dst,
                           float* __restrict__ asrc, float* __restrict__ adst,
                           int N, int H, int C) {
    int warp = (blockIdx.x * blockDim.x + threadIdx.x) >> 5;
    int lane = threadIdx.x & 31;
    if (warp >= N * H) return;
    int hh = warp % H;
    const float* hp = h + (size_t)warp * C;
    float ss = 0.f, sd = 0.f;
    for (int c = lane; c < C; c += 32) {
        float v = hp[c];
        ss += v * att_src[hh * C + c];
        sd += v * att_dst[hh * C + c];
    }
    #pragma unroll
    for (int o = 16; o; o >>= 1) {
        ss += __shfl_down_sync(0xffffffffu, ss, o);
        sd += __shfl_down_sync(0xffffffffu, sd, o);
    }
    if (lane == 0) { asrc[warp] = ss; adst[warp] = sd; }
}

// ---- layer1 edge passes ----
// pass 1: compute leaky-relu scores, stream to g_e1, atomic-max into m
__global__ void edge_pre1(const int* __restrict__ ei, int E) {
    int e = blockIdx.x * blockDim.x + threadIdx.x;
    if (e >= E) return;
    int s = ei[e], d = ei[E + e];
    const float4* as = (const float4*)(g_asrc1 + (size_t)s * 8);
    const float4* ad = (const float4*)(g_adst1 + (size_t)d * 8);
    float4 a0 = as[0], a1 = as[1], b0 = ad[0], b1 = ad[1];
    float4 e0 = make_float4(lrelu(a0.x + b0.x), lrelu(a0.y + b0.y),
                            lrelu(a0.z + b0.z), lrelu(a0.w + b0.w));
    float4 e1 = make_float4(lrelu(a1.x + b1.x), lrelu(a1.y + b1.y),
                            lrelu(a1.z + b1.z), lrelu(a1.w + b1.w));
    float4* ep = (float4*)(g_e1 + (size_t)e * 8);
    ep[0] = e0; ep[1] = e1;
    float* mp = g_m1 + (size_t)d * 8;
    atomicMaxFloat(mp + 0, e0.x); atomicMaxFloat(mp + 1, e0.y);
    atomicMaxFloat(mp + 2, e0.z); atomicMaxFloat(mp + 3, e0.w);
    atomicMaxFloat(mp + 4, e1.x); atomicMaxFloat(mp + 5, e1.y);
    atomicMaxFloat(mp + 6, e1.z); atomicMaxFloat(mp + 7, e1.w);
}

// pass 2: ee = exp(e - m[d]), store back, accumulate denominator
__global__ void edge_sum1(const int* __restrict__ ei, int E) {
    int e = blockIdx.x * blockDim.x + threadIdx.x;
    if (e >= E) return;
    int d = ei[E + e];
    float4* ep = (float4*)(g_e1 + (size_t)e * 8);
    const float4* mp = (const float4*)(g_m1 + (size_t)d * 8);
    float4 e0 = ep[0], e1 = ep[1], m0 = mp[0], m1 = mp[1];
    e0.x = __expf(e0.x - m0.x); e0.y = __expf(e0.y - m0.y);
    e0.z = __expf(e0.z - m0.z); e0.w = __expf(e0.w - m0.w);
    e1.x = __expf(e1.x - m1.x); e1.y = __expf(e1.y - m1.y);
    e1.z = __expf(e1.z - m1.z); e1.w = __expf(e1.w - m1.w);
    ep[0] = e0; ep[1] = e1;
    float* dp = g_den1 + (size_t)d * 8;
    redAdd4(dp,     e0.x, e0.y, e0.z, e0.w);
    redAdd4(dp + 4, e1.x, e1.y, e1.z, e1.w);
}

// pass 3: warp per edge; lane handles 8 channels of head (lane>>2)
__global__ __launch_bounds__(256) void edge_agg1(const int* __restrict__ ei, int E) {
    int warp = (blockIdx.x * blockDim.x + threadIdx.x) >> 5;
    if (warp >= E) return;
    int lane = threadIdx.x & 31;
    int s = ei[warp], d = ei[E + warp];
    int h = lane >> 2;
    float ee = g_e1[(size_t)warp * 8 + h];
    float dn = g_den1[(size_t)d * 8 + h];
    float alpha = ee / (dn + EPS_F);
    const float* hs = g_h1 + (size_t)s * H1C + lane * 8;
    float* po       = g_out1 + (size_t)d * H1C + lane * 8;
    float4 v0 = *(const float4*)hs;
    float4 v1 = *(const float4*)(hs + 4);
    redAdd4(po,     v0.x * alpha, v0.y * alpha, v0.z * alpha, v0.w * alpha);
    redAdd4(po + 4, v1.x * alpha, v1.y * alpha, v1.z * alpha, v1.w * alpha);
}

__global__ void elu_bias_kernel(const float* __restrict__ bias, int n) {
    int i = blockIdx.x * blockDim.x + threadIdx.x;
    if (i >= n) return;
    float v = g_out1[i] + bias[i & (H1C - 1)];
    g_out1[i] = v > 0.0f ? v : expm1f(v);
}

// ---- layer2 edge passes (H=1, C=64); reuse g_e1 as scalar per edge ----
__global__ void edge_pre2(const int* __restrict__ ei, int E) {
    int e = blockIdx.x * blockDim.x + threadIdx.x;
    if (e >= E) return;
    int s = ei[e], d = ei[E + e];
    float ev = lrelu(g_asrc2[s] + g_adst2[d]);
    g_e1[e] = ev;
    atomicMaxFloat(g_m2 + d, ev);
}
__global__ void edge_sum2(const int* __restrict__ ei, int E) {
    int e = blockIdx.x * blockDim.x + threadIdx.x;
    if (e >= E) return;
    int d = ei[E + e];
    float ee = __expf(g_e1[e] - g_m2[d]);
    g_e1[e] = ee;
    atomicAdd(g_den2 + d, ee);
}
__global__ __launch_bounds__(256) void edge_agg2(const int* __restrict__ ei, int E,
                                                 float* __restrict__ out) {
    int warp = (blockIdx.x * blockDim.x + threadIdx.x) >> 5;
    if (warp >= E) return;
    int lane = threadIdx.x & 31;
    int s = ei[warp], d = ei[E + warp];
    float alpha = g_e1[warp] / (g_den2[d] + EPS_F);
    const float* hs = g_h2 + (size_t)s * OUT_C + lane * 2;
    float* po       = out + (size_t)d * OUT_C + lane * 2;
    redAdd2(po, hs[0] * alpha, hs[1] * alpha);
}

__global__ void bias2_kernel(float* __restrict__ out, const float* __restrict__ bias, int n) {
    int i = blockIdx.x * blockDim.x + threadIdx.x;
    if (i >= n) return;
    out[i] += bias[i & (OUT_C - 1)];
}

extern "C" void kernel_launch(void* const* d_in, const int* in_sizes, int n_in,
                              void* d_out, int out_size) {
    const float* x        = (const float*)d_in[0];
    const int*   ei       = (const int*)d_in[1];
    const float* W1       = (const float*)d_in[2];
    const float* att_src1 = (const float*)d_in[3];
    const float* att_dst1 = (const float*)d_in[4];
    const float* bias1    = (const float*)d_in[5];
    const float* W2       = (const float*)d_in[6];
    const float* att_src2 = (const float*)d_in[7];
    const float* att_dst2 = (const float*)d_in[8];
    const float* bias2    = (const float*)d_in[9];
    float* out = (float*)d_out;

    const int N = in_sizes[0] / IN_C;
    const int E = in_sizes[1] / 2;

    float *p_out1, *p_m1, *p_den1, *p_m2, *p_den2, *p_h1, *p_h2;
    float *p_as1, *p_ad1, *p_as2, *p_ad2;
    cudaGetSymbolAddress((void**)&p_out1, g_out1);
    cudaGetSymbolAddress((void**)&p_m1,   g_m1);
    cudaGetSymbolAddress((void**)&p_den1, g_den1);
    cudaGetSymbolAddress((void**)&p_m2,   g_m2);
    cudaGetSymbolAddress((void**)&p_den2, g_den2);
    cudaGetSymbolAddress((void**)&p_h1,   g_h1);
    cudaGetSymbolAddress((void**)&p_h2,   g_h2);
    cudaGetSymbolAddress((void**)&p_as1,  g_asrc1);
    cudaGetSymbolAddress((void**)&p_ad1,  g_adst1);
    cudaGetSymbolAddress((void**)&p_as2,  g_asrc2);
    cudaGetSymbolAddress((void**)&p_ad2,  g_adst2);

    const float NEG_INF = -__builtin_huge_valf();
    const int T = 256;

    fill_kernel<<<(N * H1C + T - 1) / T, T>>>(p_out1, N * H1C, 0.0f);
    fill_kernel<<<(N * HEADS + T - 1) / T, T>>>(p_m1, N * HEADS, NEG_INF);
    fill_kernel<<<(N * HEADS + T - 1) / T, T>>>(p_den1, N * HEADS, 0.0f);
    fill_kernel<<<(N + T - 1) / T, T>>>(p_m2, N, NEG_INF);
    fill_kernel<<<(N + T - 1) / T, T>>>(p_den2, N, 0.0f);
    fill_kernel<<<(N * OUT_C + T - 1) / T, T>>>(out, N * OUT_C, 0.0f);

    {
        dim3 grid(H1C / 64, (N + 127) / 128);
        sgemm128x64<<<grid, 256>>>(x, W1, p_h1, N, H1C, IN_C);
    }
    att_kernel<<<(N * HEADS * 32 + T - 1) / T, T>>>(p_h1, att_src1, att_dst1,
                                                    p_as1, p_ad1, N, HEADS, HID);
    edge_pre1<<<(E + T - 1) / T, T>>>(ei, E);
    edge_sum1<<<(E + T - 1) / T, T>>>(ei, E);
    edge_agg1<<<(int)(((size_t)E * 32 + T - 1) / T), T>>>(ei, E);
    elu_bias_kernel<<<(N * H1C + T - 1) / T, T>>>(bias1, N * H1C);

    {
        dim3 grid(OUT_C / 64, (N + 127) / 128);
        sgemm128x64<<<grid, 256>>>(p_out1, W2, p_h2, N, OUT_C, H1C);
    }
    att_kernel<<<(N * 32 + T - 1) / T, T>>>(p_h2, att_src2, att_dst2,
                                            p_as2, p_ad2, N, 1, OUT_C);
    edge_pre2<<<(E + T - 1) / T, T>>>(ei, E);
    edge_sum2<<<(E + T - 1) / T, T>>>(ei, E);
    edge_agg2<<<(int)(((size_t)E * 32 + T - 1) / T), T>>>(ei, E, out);
    bias2_kernel<<<(N * OUT_C + T - 1) / T, T>>>(out, bias2, N * OUT_C);
}

// round 4
// speedup vs baseline: 1.2307x; 1.1532x over previous
#include <cuda_runtime.h>
#include <cuda_bf16.h>
#include <math.h>

#define NN 50000
#define NE 800000
#define IN_C 128
#define HID 32
#define HEADS 8
#define H1C (HEADS*HID)   // 256
#define OUT_C 64
#define NEG_SLOPE 0.2f
#define EPS_F 1e-16f

__device__ float g_h1[(size_t)NN * H1C];
__device__ float g_out1[(size_t)NN * H1C];
__device__ float g_h2[(size_t)NN * OUT_C];
__device__ float g_e1[(size_t)NE * HEADS];   // per-edge ee values
__device__ float g_asrc1[NN * HEADS];
__device__ float g_adst1[NN * HEADS];
__device__ float g_den1[NN * HEADS];
__device__ float g_asrc2[NN];
__device__ float g_adst2[NN];
__device__ float g_den2[NN];

__device__ __forceinline__ void redAdd4(float* p, float a, float b, float c, float d) {
    asm volatile("red.global.add.v4.f32 [%0], {%1,%2,%3,%4};"
                 :: "l"(p), "f"(a), "f"(b), "f"(c), "f"(d) : "memory");
}
__device__ __forceinline__ void redAdd2(float* p, float a, float b) {
    asm volatile("red.global.add.v2.f32 [%0], {%1,%2};"
                 :: "l"(p), "f"(a), "f"(b) : "memory");
}
__device__ __forceinline__ float lrelu(float x) { return x >= 0.0f ? x : NEG_SLOPE * x; }
__device__ __forceinline__ unsigned f2tf32(float f) {
    unsigned u;
    asm("cvt.rna.tf32.f32 %0, %1;" : "=r"(u) : "f"(f));
    return u;
}

__global__ void fill_kernel(float* __restrict__ p, int n, float v) {
    int i = blockIdx.x * blockDim.x + threadIdx.x;
    if (i < n) p[i] = v;
}

// ---------------- tf32 tensor-core GEMM ----------------
// C[M,N] = A[M,K] @ B[K,N].  BM=128, BN=64, BK=16. 256 thr = 8 warps (4M x 2N),
// warp tile 32x32, mma.m16n8k8 tf32. Requires N%64==0, K%16==0.
#define AS_STRIDE 20
#define BS_STRIDE 20
__global__ __launch_bounds__(256) void gemm_tf32(const float* __restrict__ A,
                                                 const float* __restrict__ B,
                                                 float* __restrict__ C,
                                                 int M, int N, int K) {
    __shared__ unsigned As[128][AS_STRIDE];  // tf32 bits, [m][k]
    __shared__ unsigned Bs[64][BS_STRIDE];   // tf32 bits, [n][k] (transposed)
    int t = threadIdx.x;
    int lane = t & 31, w = t >> 5;
    int wm = (w & 3) * 32;      // warp M offset in tile
    int wn = (w >> 2) * 32;     // warp N offset in tile
    int blockRow = blockIdx.y * 128;
    int blockCol = blockIdx.x * 64;

    float acc[2][4][4];
    #pragma unroll
    for (int i = 0; i < 2; i++)
        #pragma unroll
        for (int j = 0; j < 4; j++)
            #pragma unroll
            for (int q = 0; q < 4; q++) acc[i][j][q] = 0.0f;

    // A tile loader: thread loads row t>>1, cols (t&1)*8 .. +7
    int aRow = t >> 1, aColBase = (t & 1) * 8;
    int gRowA = blockRow + aRow;
    // B tile loader: thread loads B row t>>4 (k), cols (t&15)*4 (n)
    int bK = t >> 4, bN = (t & 15) * 4;

    for (int k0 = 0; k0 < K; k0 += 16) {
        // stage A
        float4 a0v = make_float4(0.f,0.f,0.f,0.f), a1v = a0v;
        if (gRowA < M) {
            const float* ap = A + (size_t)gRowA * K + k0 + aColBase;
            a0v = *(const float4*)ap;
            a1v = *(const float4*)(ap + 4);
        }
        As[aRow][aColBase + 0] = f2tf32(a0v.x); As[aRow][aColBase + 1] = f2tf32(a0v.y);
        As[aRow][aColBase + 2] = f2tf32(a0v.z); As[aRow][aColBase + 3] = f2tf32(a0v.w);
        As[aRow][aColBase + 4] = f2tf32(a1v.x); As[aRow][aColBase + 5] = f2tf32(a1v.y);
        As[aRow][aColBase + 6] = f2tf32(a1v.z); As[aRow][aColBase + 7] = f2tf32(a1v.w);
        // stage B (transpose to [n][k])
        {
            float4 bv = *(const float4*)(B + (size_t)(k0 + bK) * N + blockCol + bN);
            Bs[bN + 0][bK] = f2tf32(bv.x);
            Bs[bN + 1][bK] = f2tf32(bv.y);
            Bs[bN + 2][bK] = f2tf32(bv.z);
            Bs[bN + 3][bK] = f2tf32(bv.w);
        }
        __syncthreads();

        int lr = lane >> 2, lc = lane & 3;
        #pragma unroll
        for (int ks = 0; ks < 2; ks++) {
            int kb = ks * 8;
            unsigned af[2][4], bf[4][2];
            #pragma unroll
            for (int ms = 0; ms < 2; ms++) {
                int mb = wm + ms * 16;
                af[ms][0] = As[mb + lr     ][kb + lc];
                af[ms][1] = As[mb + 8 + lr ][kb + lc];
                af[ms][2] = As[mb + lr     ][kb + 4 + lc];
                af[ms][3] = As[mb + 8 + lr ][kb + 4 + lc];
            }
            #pragma unroll
            for (int ns = 0; ns < 4; ns++) {
                int nb = wn + ns * 8;
                bf[ns][0] = Bs[nb + lr][kb + lc];
                bf[ns][1] = Bs[nb + lr][kb + 4 + lc];
            }
            #pragma unroll
            for (int ms = 0; ms < 2; ms++)
                #pragma unroll
                for (int ns = 0; ns < 4; ns++) {
                    asm volatile(
                        "mma.sync.aligned.m16n8k8.row.col.f32.tf32.tf32.f32 "
                        "{%0,%1,%2,%3}, {%4,%5,%6,%7}, {%8,%9}, {%0,%1,%2,%3};"
                        : "+f"(acc[ms][ns][0]), "+f"(acc[ms][ns][1]),
                          "+f"(acc[ms][ns][2]), "+f"(acc[ms][ns][3])
                        : "r"(af[ms][0]), "r"(af[ms][1]), "r"(af[ms][2]), "r"(af[ms][3]),
                          "r"(bf[ns][0]), "r"(bf[ns][1]));
                }
        }
        __syncthreads();
    }

    // store: c0,c1 at (row, col..col+1); c2,c3 at (row+8, ...)
    int lr = lane >> 2, lc = lane & 3;
    #pragma unroll
    for (int ms = 0; ms < 2; ms++) {
        int row0 = blockRow + wm + ms * 16 + lr;
        #pragma unroll
        for (int ns = 0; ns < 4; ns++) {
            int col = blockCol + wn + ns * 8 + lc * 2;
            if (row0 < M) {
                float2 v = make_float2(acc[ms][ns][0], acc[ms][ns][1]);
                *(float2*)(C + (size_t)row0 * N + col) = v;
            }
            if (row0 + 8 < M) {
                float2 v = make_float2(acc[ms][ns][2], acc[ms][ns][3]);
                *(float2*)(C + (size_t)(row0 + 8) * N + col) = v;
            }
        }
    }
}

// ---------------- attention coefficients ----------------
__global__ void att_kernel(const float* __restrict__ h,
                           const float* __restrict__ att_src,
                           const float* __restrict__ att_dst,
                           float* __restrict__ asrc, float* __restrict__ adst,
                           int N, int H, int C) {
    int warp = (blockIdx.x * blockDim.x + threadIdx.x) >> 5;
    int lane = threadIdx.x & 31;
    if (warp >= N * H) return;
    int hh = warp % H;
    const float* hp = h + (size_t)warp * C;
    float ss = 0.f, sd = 0.f;
    for (int c = lane; c < C; c += 32) {
        float v = hp[c];
        ss += v * att_src[hh * C + c];
        sd += v * att_dst[hh * C + c];
    }
    #pragma unroll
    for (int o = 16; o; o >>= 1) {
        ss += __shfl_down_sync(0xffffffffu, ss, o);
        sd += __shfl_down_sync(0xffffffffu, sd, o);
    }
    if (lane == 0) { asrc[warp] = ss; adst[warp] = sd; }
}

// ---------------- layer1 edge passes (no max pass; exp is safe) ----------------
// pass 1: ee = exp(lrelu(asrc[s]+adst[d])), store, accumulate denominator
__global__ void edge_score1(const int* __restrict__ ei, int E) {
    int e = blockIdx.x * blockDim.x + threadIdx.x;
    if (e >= E) return;
    int s = ei[e], d = ei[E + e];
    const float4* as = (const float4*)(g_asrc1 + (size_t)s * 8);
    const float4* ad = (const float4*)(g_adst1 + (size_t)d * 8);
    float4 a0 = as[0], a1 = as[1], b0 = ad[0], b1 = ad[1];
    float4 e0 = make_float4(__expf(lrelu(a0.x + b0.x)), __expf(lrelu(a0.y + b0.y)),
                            __expf(lrelu(a0.z + b0.z)), __expf(lrelu(a0.w + b0.w)));
    float4 e1 = make_float4(__expf(lrelu(a1.x + b1.x)), __expf(lrelu(a1.y + b1.y)),
                            __expf(lrelu(a1.z + b1.z)), __expf(lrelu(a1.w + b1.w)));
    float4* ep = (float4*)(g_e1 + (size_t)e * 8);
    ep[0] = e0; ep[1] = e1;
    float* dp = g_den1 + (size_t)d * 8;
    redAdd4(dp,     e0.x, e0.y, e0.z, e0.w);
    redAdd4(dp + 4, e1.x, e1.y, e1.z, e1.w);
}

// pass 2: warp per edge; lane handles 8 channels of head (lane>>2)
__global__ __launch_bounds__(256) void edge_agg1(const int* __restrict__ ei, int E) {
    int warp = (blockIdx.x * blockDim.x + threadIdx.x) >> 5;
    if (warp >= E) return;
    int lane = threadIdx.x & 31;
    int s = ei[warp], d = ei[E + warp];
    int h = lane >> 2;
    float ee = g_e1[(size_t)warp * 8 + h];
    float dn = g_den1[(size_t)d * 8 + h];
    float alpha = ee / (dn + EPS_F);
    const float* hs = g_h1 + (size_t)s * H1C + lane * 8;
    float* po       = g_out1 + (size_t)d * H1C + lane * 8;
    float4 v0 = *(const float4*)hs;
    float4 v1 = *(const float4*)(hs + 4);
    redAdd4(po,     v0.x * alpha, v0.y * alpha, v0.z * alpha, v0.w * alpha);
    redAdd4(po + 4, v1.x * alpha, v1.y * alpha, v1.z * alpha, v1.w * alpha);
}

__global__ void elu_bias_kernel(const float* __restrict__ bias, int n) {
    int i = blockIdx.x * blockDim.x + threadIdx.x;
    if (i >= n) return;
    float v = g_out1[i] + bias[i & (H1C - 1)];
    g_out1[i] = v > 0.0f ? v : expm1f(v);
}

// ---------------- layer2 edge passes (H=1, C=64) ----------------
__global__ void edge_score2(const int* __restrict__ ei, int E) {
    int e = blockIdx.x * blockDim.x + threadIdx.x;
    if (e >= E) return;
    int s = ei[e], d = ei[E + e];
    float ee = __expf(lrelu(g_asrc2[s] + g_adst2[d]));
    g_e1[e] = ee;
    atomicAdd(g_den2 + d, ee);
}
__global__ __launch_bounds__(256) void edge_agg2(const int* __restrict__ ei, int E,
                                                 float* __restrict__ out) {
    int warp = (blockIdx.x * blockDim.x + threadIdx.x) >> 5;
    if (warp >= E) return;
    int lane = threadIdx.x & 31;
    int s = ei[warp], d = ei[E + warp];
    float alpha = g_e1[warp] / (g_den2[d] + EPS_F);
    const float* hs = g_h2 + (size_t)s * OUT_C + lane * 2;
    float* po       = out + (size_t)d * OUT_C + lane * 2;
    redAdd2(po, hs[0] * alpha, hs[1] * alpha);
}

__global__ void bias2_kernel(float* __restrict__ out, const float* __restrict__ bias, int n) {
    int i = blockIdx.x * blockDim.x + threadIdx.x;
    if (i >= n) return;
    out[i] += bias[i & (OUT_C - 1)];
}

extern "C" void kernel_launch(void* const* d_in, const int* in_sizes, int n_in,
                              void* d_out, int out_size) {
    const float* x        = (const float*)d_in[0];
    const int*   ei       = (const int*)d_in[1];
    const float* W1       = (const float*)d_in[2];
    const float* att_src1 = (const float*)d_in[3];
    const float* att_dst1 = (const float*)d_in[4];
    const float* bias1    = (const float*)d_in[5];
    const float* W2       = (const float*)d_in[6];
    const float* att_src2 = (const float*)d_in[7];
    const float* att_dst2 = (const float*)d_in[8];
    const float* bias2    = (const float*)d_in[9];
    float* out = (float*)d_out;

    const int N = in_sizes[0] / IN_C;
    const int E = in_sizes[1] / 2;

    float *p_out1, *p_den1, *p_den2, *p_h1, *p_h2;
    float *p_as1, *p_ad1, *p_as2, *p_ad2;
    cudaGetSymbolAddress((void**)&p_out1, g_out1);
    cudaGetSymbolAddress((void**)&p_den1, g_den1);
    cudaGetSymbolAddress((void**)&p_den2, g_den2);
    cudaGetSymbolAddress((void**)&p_h1,   g_h1);
    cudaGetSymbolAddress((void**)&p_h2,   g_h2);
    cudaGetSymbolAddress((void**)&p_as1,  g_asrc1);
    cudaGetSymbolAddress((void**)&p_ad1,  g_adst1);
    cudaGetSymbolAddress((void**)&p_as2,  g_asrc2);
    cudaGetSymbolAddress((void**)&p_ad2,  g_adst2);

    const int T = 256;

    fill_kernel<<<(N * H1C + T - 1) / T, T>>>(p_out1, N * H1C, 0.0f);
    fill_kernel<<<(N * HEADS + T - 1) / T, T>>>(p_den1, N * HEADS, 0.0f);
    fill_kernel<<<(N + T - 1) / T, T>>>(p_den2, N, 0.0f);
    fill_kernel<<<(N * OUT_C + T - 1) / T, T>>>(out, N * OUT_C, 0.0f);

    {
        dim3 grid(H1C / 64, (N + 127) / 128);
        gemm_tf32<<<grid, 256>>>(x, W1, p_h1, N, H1C, IN_C);
    }
    att_kernel<<<(N * HEADS * 32 + T - 1) / T, T>>>(p_h1, att_src1, att_dst1,
                                                    p_as1, p_ad1, N, HEADS, HID);
    edge_score1<<<(E + T - 1) / T, T>>>(ei, E);
    edge_agg1<<<(int)(((size_t)E * 32 + T - 1) / T), T>>>(ei, E);
    elu_bias_kernel<<<(N * H1C + T - 1) / T, T>>>(bias1, N * H1C);

    {
        dim3 grid(OUT_C / 64, (N + 127) / 128);
        gemm_tf32<<<grid, 256>>>(p_out1, W2, p_h2, N, OUT_C, H1C);
    }
    att_kernel<<<(N * 32 + T - 1) / T, T>>>(p_h2, att_src2, att_dst2,
                                            p_as2, p_ad2, N, 1, OUT_C);
    edge_score2<<<(E + T - 1) / T, T>>>(ei, E);
    edge_agg2<<<(int)(((size_t)E * 32 + T - 1) / T), T>>>(ei, E, out);
    bias2_kernel<<<(N * OUT_C + T - 1) / T, T>>>(out, bias2, N * OUT_C);
}

// round 6
// speedup vs baseline: 2.3649x; 1.9216x over previous
#include <cuda_runtime.h>
#include <cuda_bf16.h>
#include <math.h>

#define NN 50000
#define NE 800000
#define IN_C 128
#define HID 32
#define HEADS 8
#define H1C (HEADS*HID)   // 256
#define OUT_C 64
#define NEG_SLOPE 0.2f
#define EPS_F 1e-16f
#define SCAN_B 1024

__device__ float g_h1[(size_t)NN * H1C];
__device__ float g_out1[(size_t)NN * H1C];
__device__ float g_h2[(size_t)NN * OUT_C];
__device__ float g_asrc1[NN * HEADS];
__device__ float g_adst1[NN * HEADS];
__device__ float g_asrc2[NN];
__device__ float g_adst2[NN];
// CSR (by dst)
__device__ int g_deg[NN];
__device__ int g_off[NN];
__device__ int g_cur[NN];
__device__ int g_esrc[NE];
__device__ int g_bsum[(NN + SCAN_B - 1) / SCAN_B];
__device__ int g_boff[(NN + SCAN_B - 1) / SCAN_B];

__device__ __forceinline__ float lrelu(float x) { return x >= 0.0f ? x : NEG_SLOPE * x; }
__device__ __forceinline__ unsigned f2tf32(float f) {
    unsigned u;
    asm("cvt.rna.tf32.f32 %0, %1;" : "=r"(u) : "f"(f));
    return u;
}

__global__ void ifill_kernel(int* __restrict__ p, int n, int v) {
    int i = blockIdx.x * blockDim.x + threadIdx.x;
    if (i < n) p[i] = v;
}

// ---------------- CSR build ----------------
__global__ void hist_kernel(const int* __restrict__ ei, int E) {
    int e = blockIdx.x * blockDim.x + threadIdx.x;
    if (e >= E) return;
    atomicAdd(&g_deg[ei[E + e]], 1);
}

__global__ void scan1_kernel(int n) {
    __shared__ int sm[SCAN_B];
    int b = blockIdx.x, t = threadIdx.x;
    int i = b * SCAN_B + t;
    int v = (i < n) ? g_deg[i] : 0;
    sm[t] = v;
    __syncthreads();
    #pragma unroll
    for (int o = 1; o < SCAN_B; o <<= 1) {
        int u = (t >= o) ? sm[t - o] : 0;
        __syncthreads();
        sm[t] += u;
        __syncthreads();
    }
    if (i < n) g_off[i] = sm[t] - v;   // exclusive
    if (t == SCAN_B - 1) g_bsum[b] = sm[t];
}

__global__ void scan2_kernel(int nb) {
    __shared__ int sm[SCAN_B];
    int t = threadIdx.x;
    int v = (t < nb) ? g_bsum[t] : 0;
    sm[t] = v;
    __syncthreads();
    #pragma unroll
    for (int o = 1; o < SCAN_B; o <<= 1) {
        int u = (t >= o) ? sm[t - o] : 0;
        __syncthreads();
        sm[t] += u;
        __syncthreads();
    }
    if (t < nb) g_boff[t] = sm[t] - v;  // exclusive block offsets
}

__global__ void scan3_kernel(int n) {
    int i = blockIdx.x * blockDim.x + threadIdx.x;
    if (i < n) g_off[i] += g_boff[i / SCAN_B];
}

__global__ void scatter_kernel(const int* __restrict__ ei, int E) {
    int e = blockIdx.x * blockDim.x + threadIdx.x;
    if (e >= E) return;
    int s = ei[e], d = ei[E + e];
    int pos = atomicAdd(&g_cur[d], 1);
    g_esrc[g_off[d] + pos] = s;
}

// ---------------- tf32 tensor-core GEMM ----------------
#define AS_STRIDE 20
#define BS_STRIDE 20
__global__ __launch_bounds__(256) void gemm_tf32(const float* __restrict__ A,
                                                 const float* __restrict__ B,
                                                 float* __restrict__ C,
                                                 int M, int N, int K) {
    __shared__ unsigned As[128][AS_STRIDE];
    __shared__ unsigned Bs[64][BS_STRIDE];
    int t = threadIdx.x;
    int lane = t & 31, w = t >> 5;
    int wm = (w & 3) * 32;
    int wn = (w >> 2) * 32;
    int blockRow = blockIdx.y * 128;
    int blockCol = blockIdx.x * 64;

    float acc[2][4][4];
    #pragma unroll
    for (int i = 0; i < 2; i++)
        #pragma unroll
        for (int j = 0; j < 4; j++)
            #pragma unroll
            for (int q = 0; q < 4; q++) acc[i][j][q] = 0.0f;

    int aRow = t >> 1, aColBase = (t & 1) * 8;
    int gRowA = blockRow + aRow;
    int bK = t >> 4, bN = (t & 15) * 4;

    for (int k0 = 0; k0 < K; k0 += 16) {
        float4 a0v = make_float4(0.f,0.f,0.f,0.f), a1v = a0v;
        if (gRowA < M) {
            const float* ap = A + (size_t)gRowA * K + k0 + aColBase;
            a0v = *(const float4*)ap;
            a1v = *(const float4*)(ap + 4);
        }
        As[aRow][aColBase + 0] = f2tf32(a0v.x); As[aRow][aColBase + 1] = f2tf32(a0v.y);
        As[aRow][aColBase + 2] = f2tf32(a0v.z); As[aRow][aColBase + 3] = f2tf32(a0v.w);
        As[aRow][aColBase + 4] = f2tf32(a1v.x); As[aRow][aColBase + 5] = f2tf32(a1v.y);
        As[aRow][aColBase + 6] = f2tf32(a1v.z); As[aRow][aColBase + 7] = f2tf32(a1v.w);
        {
            float4 bv = *(const float4*)(B + (size_t)(k0 + bK) * N + blockCol + bN);
            Bs[bN + 0][bK] = f2tf32(bv.x);
            Bs[bN + 1][bK] = f2tf32(bv.y);
            Bs[bN + 2][bK] = f2tf32(bv.z);
            Bs[bN + 3][bK] = f2tf32(bv.w);
        }
        __syncthreads();

        int lr = lane >> 2, lc = lane & 3;
        #pragma unroll
        for (int ks = 0; ks < 2; ks++) {
            int kb = ks * 8;
            unsigned af[2][4], bf[4][2];
            #pragma unroll
            for (int ms = 0; ms < 2; ms++) {
                int mb = wm + ms * 16;
                af[ms][0] = As[mb + lr     ][kb + lc];
                af[ms][1] = As[mb + 8 + lr ][kb + lc];
                af[ms][2] = As[mb + lr     ][kb + 4 + lc];
                af[ms][3] = As[mb + 8 + lr ][kb + 4 + lc];
            }
            #pragma unroll
            for (int ns = 0; ns < 4; ns++) {
                int nb = wn + ns * 8;
                bf[ns][0] = Bs[nb + lr][kb + lc];
                bf[ns][1] = Bs[nb + lr][kb + 4 + lc];
            }
            #pragma unroll
            for (int ms = 0; ms < 2; ms++)
                #pragma unroll
                for (int ns = 0; ns < 4; ns++) {
                    asm volatile(
                        "mma.sync.aligned.m16n8k8.row.col.f32.tf32.tf32.f32 "
                        "{%0,%1,%2,%3}, {%4,%5,%6,%7}, {%8,%9}, {%0,%1,%2,%3};"
                        : "+f"(acc[ms][ns][0]), "+f"(acc[ms][ns][1]),
                          "+f"(acc[ms][ns][2]), "+f"(acc[ms][ns][3])
                        : "r"(af[ms][0]), "r"(af[ms][1]), "r"(af[ms][2]), "r"(af[ms][3]),
                          "r"(bf[ns][0]), "r"(bf[ns][1]));
                }
        }
        __syncthreads();
    }

    int lr = lane >> 2, lc = lane & 3;
    #pragma unroll
    for (int ms = 0; ms < 2; ms++) {
        int row0 = blockRow + wm + ms * 16 + lr;
        #pragma unroll
        for (int ns = 0; ns < 4; ns++) {
            int col = blockCol + wn + ns * 8 + lc * 2;
            if (row0 < M) {
                float2 v = make_float2(acc[ms][ns][0], acc[ms][ns][1]);
                *(float2*)(C + (size_t)row0 * N + col) = v;
            }
            if (row0 + 8 < M) {
                float2 v = make_float2(acc[ms][ns][2], acc[ms][ns][3]);
                *(float2*)(C + (size_t)(row0 + 8) * N + col) = v;
            }
        }
    }
}

// ---------------- attention coefficients ----------------
__global__ void att_kernel(const float* __restrict__ h,
                           const float* __restrict__ att_src,
                           const float* __restrict__ att_dst,
                           float* __restrict__ asrc, float* __restrict__ adst,
                           int N, int H, int C) {
    int warp = (blockIdx.x * blockDim.x + threadIdx.x) >> 5;
    int lane = threadIdx.x & 31;
    if (warp >= N * H) return;
    int hh = warp % H;
    const float* hp = h + (size_t)warp * C;
    float ss = 0.f, sd = 0.f;
    for (int c = lane; c < C; c += 32) {
        float v = hp[c];
        ss += v * att_src[hh * C + c];
        sd += v * att_dst[hh * C + c];
    }
    #pragma unroll
    for (int o = 16; o; o >>= 1) {
        ss += __shfl_down_sync(0xffffffffu, ss, o);
        sd += __shfl_down_sync(0xffffffffu, sd, o);
    }
    if (lane == 0) { asrc[warp] = ss; adst[warp] = sd; }
}

// ---------------- layer1: warp per dst node, gather-only, fused bias+elu ----------------
__global__ __launch_bounds__(256) void csr_agg1(const float* __restrict__ bias, int N) {
    int warp = (blockIdx.x * blockDim.x + threadIdx.x) >> 5;
    if (warp >= N) return;
    int lane = threadIdx.x & 31;
    int d = warp;
    int start = g_off[d], deg = g_deg[d];
    int h = lane >> 2;
    float adst_h = g_adst1[d * 8 + h];

    // pass 1: denominator for head h
    float den = 0.f;
    for (int base = 0; base < deg; base += 32) {
        int cnt = min(32, deg - base);
        int s_reg = (base + lane < deg) ? g_esrc[start + base + lane] : 0;
        for (int j = 0; j < cnt; j++) {
            int s = __shfl_sync(0xffffffffu, s_reg, j);
            den += __expf(lrelu(g_asrc1[s * 8 + h] + adst_h));
        }
    }
    float inv = 1.0f / (den + EPS_F);

    // pass 2: weighted aggregation; lane covers channels lane*8..lane*8+7
    float4 acc0 = make_float4(0.f,0.f,0.f,0.f);
    float4 acc1 = make_float4(0.f,0.f,0.f,0.f);
    for (int base = 0; base < deg; base += 32) {
        int cnt = min(32, deg - base);
        int s_reg = (base + lane < deg) ? g_esrc[start + base + lane] : 0;
        for (int j = 0; j < cnt; j++) {
            int s = __shfl_sync(0xffffffffu, s_reg, j);
            float alpha = __expf(lrelu(g_asrc1[s * 8 + h] + adst_h)) * inv;
            const float4* hp = (const float4*)(g_h1 + (size_t)s * H1C + lane * 8);
            float4 v0 = hp[0], v1 = hp[1];
            acc0.x += alpha * v0.x; acc0.y += alpha * v0.y;
            acc0.z += alpha * v0.z; acc0.w += alpha * v0.w;
            acc1.x += alpha * v1.x; acc1.y += alpha * v1.y;
            acc1.z += alpha * v1.z; acc1.w += alpha * v1.w;
        }
    }
    // epilogue: bias + elu, single write
    const float4* bp = (const float4*)(bias + lane * 8);
    float4 b0 = bp[0], b1 = bp[1];
    float4 o0, o1;
    o0.x = acc0.x + b0.x; o0.y = acc0.y + b0.y; o0.z = acc0.z + b0.z; o0.w = acc0.w + b0.w;
    o1.x = acc1.x + b1.x; o1.y = acc1.y + b1.y; o1.z = acc1.z + b1.z; o1.w = acc1.w + b1.w;
    o0.x = o0.x > 0.f ? o0.x : expm1f(o0.x);
    o0.y = o0.y > 0.f ? o0.y : expm1f(o0.y);
    o0.z = o0.z > 0.f ? o0.z : expm1f(o0.z);
    o0.w = o0.w > 0.f ? o0.w : expm1f(o0.w);
    o1.x = o1.x > 0.f ? o1.x : expm1f(o1.x);
    o1.y = o1.y > 0.f ? o1.y : expm1f(o1.y);
    o1.z = o1.z > 0.f ? o1.z : expm1f(o1.z);
    o1.w = o1.w > 0.f ? o1.w : expm1f(o1.w);
    float4* op = (float4*)(g_out1 + (size_t)d * H1C + lane * 8);
    op[0] = o0; op[1] = o1;
}

// ---------------- layer2: warp per dst node, fused bias ----------------
__global__ __launch_bounds__(256) void csr_agg2(const float* __restrict__ bias,
                                                float* __restrict__ out, int N) {
    int warp = (blockIdx.x * blockDim.x + threadIdx.x) >> 5;
    if (warp >= N) return;
    int lane = threadIdx.x & 31;
    int d = warp;
    int start = g_off[d], deg = g_deg[d];
    float adst = g_adst2[d];

    float den = 0.f;
    for (int base = 0; base < deg; base += 32) {
        int cnt = min(32, deg - base);
        int s_reg = (base + lane < deg) ? g_esrc[start + base + lane] : 0;
        for (int j = 0; j < cnt; j++) {
            int s = __shfl_sync(0xffffffffu, s_reg, j);
            den += __expf(lrelu(g_asrc2[s] + adst));
        }
    }
    float inv = 1.0f / (den + EPS_F);

    float2 acc = make_float2(0.f, 0.f);
    for (int base = 0; base < deg; base += 32) {
        int cnt = min(32, deg - base);
        int s_reg = (base + lane < deg) ? g_esrc[start + base + lane] : 0;
        for (int j = 0; j < cnt; j++) {
            int s = __shfl_sync(0xffffffffu, s_reg, j);
            float alpha = __expf(lrelu(g_asrc2[s] + adst)) * inv;
            const float2* hp = (const float2*)(g_h2 + (size_t)s * OUT_C + lane * 2);
            float2 v = hp[0];
            acc.x += alpha * v.x; acc.y += alpha * v.y;
        }
    }
    const float2* bp = (const float2*)(bias + lane * 2);
    float2 b = bp[0];
    float2 o = make_float2(acc.x + b.x, acc.y + b.y);
    *(float2*)(out + (size_t)d * OUT_C + lane * 2) = o;
}

extern "C" void kernel_launch(void* const* d_in, const int* in_sizes, int n_in,
                              void* d_out, int out_size) {
    const float* x        = (const float*)d_in[0];
    const int*   ei       = (const int*)d_in[1];
    const float* W1       = (const float*)d_in[2];
    const float* att_src1 = (const float*)d_in[3];
    const float* att_dst1 = (const float*)d_in[4];
    const float* bias1    = (const float*)d_in[5];
    const float* W2       = (const float*)d_in[6];
    const float* att_src2 = (const float*)d_in[7];
    const float* att_dst2 = (const float*)d_in[8];
    const float* bias2    = (const float*)d_in[9];
    float* out = (float*)d_out;

    const int N = in_sizes[0] / IN_C;
    const int E = in_sizes[1] / 2;
    const int NB = (N + SCAN_B - 1) / SCAN_B;

    float *p_h1, *p_out1, *p_h2;
    float *p_as1, *p_ad1, *p_as2, *p_ad2;
    int *p_deg, *p_cur;
    cudaGetSymbolAddress((void**)&p_h1,   g_h1);
    cudaGetSymbolAddress((void**)&p_out1, g_out1);
    cudaGetSymbolAddress((void**)&p_h2,   g_h2);
    cudaGetSymbolAddress((void**)&p_as1,  g_asrc1);
    cudaGetSymbolAddress((void**)&p_ad1,  g_adst1);
    cudaGetSymbolAddress((void**)&p_as2,  g_asrc2);
    cudaGetSymbolAddress((void**)&p_ad2,  g_adst2);
    cudaGetSymbolAddress((void**)&p_deg,  g_deg);
    cudaGetSymbolAddress((void**)&p_cur,  g_cur);

    const int T = 256;

    // ---- CSR build (independent of features) ----
    ifill_kernel<<<(N + T - 1) / T, T>>>(p_deg, N, 0);
    ifill_kernel<<<(N + T - 1) / T, T>>>(p_cur, N, 0);
    hist_kernel<<<(E + T - 1) / T, T>>>(ei, E);
    scan1_kernel<<<NB, SCAN_B>>>(N);
    scan2_kernel<<<1, SCAN_B>>>(NB);
    scan3_kernel<<<(N + T - 1) / T, T>>>(N);
    scatter_kernel<<<(E + T - 1) / T, T>>>(ei, E);

    // ---- layer 1 ----
    {
        dim3 grid(H1C / 64, (N + 127) / 128);
        gemm_tf32<<<grid, 256>>>(x, W1, p_h1, N, H1C, IN_C);
    }
    att_kernel<<<(N * HEADS * 32 + T - 1) / T, T>>>(p_h1, att_src1, att_dst1,
                                                    p_as1, p_ad1, N, HEADS, HID);
    csr_agg1<<<(int)(((size_t)N * 32 + T - 1) / T), T>>>(bias1, N);

    // ---- layer 2 ----
    {
        dim3 grid(OUT_C / 64, (N + 127) / 128);
        gemm_tf32<<<grid, 256>>>(p_out1, W2, p_h2, N, OUT_C, H1C);
    }
    att_kernel<<<(N * 32 + T - 1) / T, T>>>(p_h2, att_src2, att_dst2,
                                            p_as2, p_ad2, N, 1, OUT_C);
    csr_agg2<<<(int)(((size_t)N * 32 + T - 1) / T), T>>>(bias2, out, N);
}

// round 7
// speedup vs baseline: 2.5659x; 1.0850x over previous
#include <cuda_runtime.h>
#include <cuda_fp16.h>
#include <math.h>

#define NN 50000
#define NE 800000
#define IN_C 128
#define HID 32
#define HEADS 8
#define H1C (HEADS*HID)   // 256
#define OUT_C 64
#define NEG_SLOPE 0.2f
#define EPS_F 1e-16f
#define SCAN_B 1024

__device__ __half g_h1h[(size_t)NN * H1C];   // layer1 features, fp16
__device__ float  g_out1[(size_t)NN * H1C];  // layer1 output (GEMM2 A), fp32
__device__ __half g_h2h[(size_t)NN * OUT_C]; // layer2 features, fp16
__device__ float g_asrc1[NN * HEADS];
__device__ float g_adst1[NN * HEADS];
__device__ float g_asrc2[NN];
__device__ float g_adst2[NN];
// CSR (by dst)
__device__ int g_deg[NN];
__device__ int g_off[NN];
__device__ int g_cur[NN];
__device__ int g_esrc[NE];
__device__ int g_bsum[(NN + SCAN_B - 1) / SCAN_B];
__device__ int g_boff[(NN + SCAN_B - 1) / SCAN_B];

__device__ __forceinline__ float lrelu(float x) { return x >= 0.0f ? x : NEG_SLOPE * x; }
__device__ __forceinline__ unsigned f2tf32(float f) {
    unsigned u;
    asm("cvt.rna.tf32.f32 %0, %1;" : "=r"(u) : "f"(f));
    return u;
}

__global__ void ifill_kernel(int* __restrict__ p, int n, int v) {
    int i = blockIdx.x * blockDim.x + threadIdx.x;
    if (i < n) p[i] = v;
}

// ---------------- CSR build ----------------
__global__ void hist_kernel(const int* __restrict__ ei, int E) {
    int e = blockIdx.x * blockDim.x + threadIdx.x;
    if (e >= E) return;
    atomicAdd(&g_deg[ei[E + e]], 1);
}

__global__ void scan1_kernel(int n) {
    __shared__ int sm[SCAN_B];
    int b = blockIdx.x, t = threadIdx.x;
    int i = b * SCAN_B + t;
    int v = (i < n) ? g_deg[i] : 0;
    sm[t] = v;
    __syncthreads();
    #pragma unroll
    for (int o = 1; o < SCAN_B; o <<= 1) {
        int u = (t >= o) ? sm[t - o] : 0;
        __syncthreads();
        sm[t] += u;
        __syncthreads();
    }
    if (i < n) g_off[i] = sm[t] - v;
    if (t == SCAN_B - 1) g_bsum[b] = sm[t];
}

__global__ void scan2_kernel(int nb) {
    __shared__ int sm[SCAN_B];
    int t = threadIdx.x;
    int v = (t < nb) ? g_bsum[t] : 0;
    sm[t] = v;
    __syncthreads();
    #pragma unroll
    for (int o = 1; o < SCAN_B; o <<= 1) {
        int u = (t >= o) ? sm[t - o] : 0;
        __syncthreads();
        sm[t] += u;
        __syncthreads();
    }
    if (t < nb) g_boff[t] = sm[t] - v;
}

__global__ void scan3_kernel(int n) {
    int i = blockIdx.x * blockDim.x + threadIdx.x;
    if (i < n) g_off[i] += g_boff[i / SCAN_B];
}

__global__ void scatter_kernel(const int* __restrict__ ei, int E) {
    int e = blockIdx.x * blockDim.x + threadIdx.x;
    if (e >= E) return;
    int s = ei[e], d = ei[E + e];
    int pos = atomicAdd(&g_cur[d], 1);
    g_esrc[g_off[d] + pos] = s;
}

// ---------------- tf32 tensor-core GEMM, fp16 output ----------------
#define AS_STRIDE 20
#define BS_STRIDE 20
__global__ __launch_bounds__(256) void gemm_tf32_h(const float* __restrict__ A,
                                                   const float* __restrict__ B,
                                                   __half* __restrict__ C,
                                                   int M, int N, int K) {
    __shared__ unsigned As[128][AS_STRIDE];
    __shared__ unsigned Bs[64][BS_STRIDE];
    int t = threadIdx.x;
    int lane = t & 31, w = t >> 5;
    int wm = (w & 3) * 32;
    int wn = (w >> 2) * 32;
    int blockRow = blockIdx.y * 128;
    int blockCol = blockIdx.x * 64;

    float acc[2][4][4];
    #pragma unroll
    for (int i = 0; i < 2; i++)
        #pragma unroll
        for (int j = 0; j < 4; j++)
            #pragma unroll
            for (int q = 0; q < 4; q++) acc[i][j][q] = 0.0f;

    int aRow = t >> 1, aColBase = (t & 1) * 8;
    int gRowA = blockRow + aRow;
    int bK = t >> 4, bN = (t & 15) * 4;

    for (int k0 = 0; k0 < K; k0 += 16) {
        float4 a0v = make_float4(0.f,0.f,0.f,0.f), a1v = a0v;
        if (gRowA < M) {
            const float* ap = A + (size_t)gRowA * K + k0 + aColBase;
            a0v = *(const float4*)ap;
            a1v = *(const float4*)(ap + 4);
        }
        As[aRow][aColBase + 0] = f2tf32(a0v.x); As[aRow][aColBase + 1] = f2tf32(a0v.y);
        As[aRow][aColBase + 2] = f2tf32(a0v.z); As[aRow][aColBase + 3] = f2tf32(a0v.w);
        As[aRow][aColBase + 4] = f2tf32(a1v.x); As[aRow][aColBase + 5] = f2tf32(a1v.y);
        As[aRow][aColBase + 6] = f2tf32(a1v.z); As[aRow][aColBase + 7] = f2tf32(a1v.w);
        {
            float4 bv = *(const float4*)(B + (size_t)(k0 + bK) * N + blockCol + bN);
            Bs[bN + 0][bK] = f2tf32(bv.x);
            Bs[bN + 1][bK] = f2tf32(bv.y);
            Bs[bN + 2][bK] = f2tf32(bv.z);
            Bs[bN + 3][bK] = f2tf32(bv.w);
        }
        __syncthreads();

        int lr = lane >> 2, lc = lane & 3;
        #pragma unroll
        for (int ks = 0; ks < 2; ks++) {
            int kb = ks * 8;
            unsigned af[2][4], bf[4][2];
            #pragma unroll
            for (int ms = 0; ms < 2; ms++) {
                int mb = wm + ms * 16;
                af[ms][0] = As[mb + lr     ][kb + lc];
                af[ms][1] = As[mb + 8 + lr ][kb + lc];
                af[ms][2] = As[mb + lr     ][kb + 4 + lc];
                af[ms][3] = As[mb + 8 + lr ][kb + 4 + lc];
            }
            #pragma unroll
            for (int ns = 0; ns < 4; ns++) {
                int nb = wn + ns * 8;
                bf[ns][0] = Bs[nb + lr][kb + lc];
                bf[ns][1] = Bs[nb + lr][kb + 4 + lc];
            }
            #pragma unroll
            for (int ms = 0; ms < 2; ms++)
                #pragma unroll
                for (int ns = 0; ns < 4; ns++) {
                    asm volatile(
                        "mma.sync.aligned.m16n8k8.row.col.f32.tf32.tf32.f32 "
                        "{%0,%1,%2,%3}, {%4,%5,%6,%7}, {%8,%9}, {%0,%1,%2,%3};"
                        : "+f"(acc[ms][ns][0]), "+f"(acc[ms][ns][1]),
                          "+f"(acc[ms][ns][2]), "+f"(acc[ms][ns][3])
                        : "r"(af[ms][0]), "r"(af[ms][1]), "r"(af[ms][2]), "r"(af[ms][3]),
                          "r"(bf[ns][0]), "r"(bf[ns][1]));
                }
        }
        __syncthreads();
    }

    int lr = lane >> 2, lc = lane & 3;
    #pragma unroll
    for (int ms = 0; ms < 2; ms++) {
        int row0 = blockRow + wm + ms * 16 + lr;
        #pragma unroll
        for (int ns = 0; ns < 4; ns++) {
            int col = blockCol + wn + ns * 8 + lc * 2;
            if (row0 < M)
                *(__half2*)(C + (size_t)row0 * N + col) =
                    __floats2half2_rn(acc[ms][ns][0], acc[ms][ns][1]);
            if (row0 + 8 < M)
                *(__half2*)(C + (size_t)(row0 + 8) * N + col) =
                    __floats2half2_rn(acc[ms][ns][2], acc[ms][ns][3]);
        }
    }
}

// ---------------- attention coefficients (fp16 features) ----------------
__global__ void att_kernel_h(const __half* __restrict__ h,
                             const float* __restrict__ att_src,
                             const float* __restrict__ att_dst,
                             float* __restrict__ asrc, float* __restrict__ adst,
                             int N, int H, int C) {
    int warp = (blockIdx.x * blockDim.x + threadIdx.x) >> 5;
    int lane = threadIdx.x & 31;
    if (warp >= N * H) return;
    int hh = warp % H;
    const __half* hp = h + (size_t)warp * C;
    float ss = 0.f, sd = 0.f;
    for (int c = lane; c < C; c += 32) {
        float v = __half2float(hp[c]);
        ss += v * att_src[hh * C + c];
        sd += v * att_dst[hh * C + c];
    }
    #pragma unroll
    for (int o = 16; o; o >>= 1) {
        ss += __shfl_down_sync(0xffffffffu, ss, o);
        sd += __shfl_down_sync(0xffffffffu, sd, o);
    }
    if (lane == 0) { asrc[warp] = ss; adst[warp] = sd; }
}

// ---------------- layer1: warp per dst node, SINGLE pass, fp16 gather ----------------
__global__ __launch_bounds__(256) void csr_agg1(const float* __restrict__ bias, int N) {
    int warp = (blockIdx.x * blockDim.x + threadIdx.x) >> 5;
    if (warp >= N) return;
    int lane = threadIdx.x & 31;
    int d = warp;
    int start = g_off[d], deg = g_deg[d];
    int h = lane >> 2;
    float adst_h = g_adst1[d * 8 + h];

    float den = 0.f;
    float acc[8];
    #pragma unroll
    for (int q = 0; q < 8; q++) acc[q] = 0.f;

    for (int base = 0; base < deg; base += 32) {
        int cnt = min(32, deg - base);
        int s_reg = (base + lane < deg) ? g_esrc[start + base + lane] : 0;
        for (int j = 0; j < cnt; j++) {
            int s = __shfl_sync(0xffffffffu, s_reg, j);
            float ee = __expf(lrelu(g_asrc1[s * 8 + h] + adst_h));
            den += ee;
            // 8 halves = 16B per lane, coalesced 512B per warp
            const __half2* hp = (const __half2*)(g_h1h + (size_t)s * H1C + lane * 8);
            #pragma unroll
            for (int q = 0; q < 4; q++) {
                float2 v = __half22float2(hp[q]);
                acc[q * 2 + 0] += ee * v.x;
                acc[q * 2 + 1] += ee * v.y;
            }
        }
    }
    float inv = 1.0f / (den + EPS_F);
    // epilogue: normalize + bias + elu, single fp32 write
    const float4* bp = (const float4*)(bias + lane * 8);
    float4 b0 = bp[0], b1 = bp[1];
    float o[8];
    o[0] = acc[0] * inv + b0.x; o[1] = acc[1] * inv + b0.y;
    o[2] = acc[2] * inv + b0.z; o[3] = acc[3] * inv + b0.w;
    o[4] = acc[4] * inv + b1.x; o[5] = acc[5] * inv + b1.y;
    o[6] = acc[6] * inv + b1.z; o[7] = acc[7] * inv + b1.w;
    #pragma unroll
    for (int q = 0; q < 8; q++) o[q] = o[q] > 0.f ? o[q] : expm1f(o[q]);
    float4* op = (float4*)(g_out1 + (size_t)d * H1C + lane * 8);
    op[0] = make_float4(o[0], o[1], o[2], o[3]);
    op[1] = make_float4(o[4], o[5], o[6], o[7]);
}

// ---------------- layer2: warp per dst node, SINGLE pass, fp16 gather ----------------
__global__ __launch_bounds__(256) void csr_agg2(const float* __restrict__ bias,
                                                float* __restrict__ out, int N) {
    int warp = (blockIdx.x * blockDim.x + threadIdx.x) >> 5;
    if (warp >= N) return;
    int lane = threadIdx.x & 31;
    int d = warp;
    int start = g_off[d], deg = g_deg[d];
    float adst = g_adst2[d];

    float den = 0.f;
    float accx = 0.f, accy = 0.f;
    for (int base = 0; base < deg; base += 32) {
        int cnt = min(32, deg - base);
        int s_reg = (base + lane < deg) ? g_esrc[start + base + lane] : 0;
        for (int j = 0; j < cnt; j++) {
            int s = __shfl_sync(0xffffffffu, s_reg, j);
            float ee = __expf(lrelu(g_asrc2[s] + adst));
            den += ee;
            float2 v = __half22float2(*(const __half2*)(g_h2h + (size_t)s * OUT_C + lane * 2));
            accx += ee * v.x; accy += ee * v.y;
        }
    }
    float inv = 1.0f / (den + EPS_F);
    const float2* bp = (const float2*)(bias + lane * 2);
    float2 b = bp[0];
    *(float2*)(out + (size_t)d * OUT_C + lane * 2) =
        make_float2(accx * inv + b.x, accy * inv + b.y);
}

extern "C" void kernel_launch(void* const* d_in, const int* in_sizes, int n_in,
                              void* d_out, int out_size) {
    const float* x        = (const float*)d_in[0];
    const int*   ei       = (const int*)d_in[1];
    const float* W1       = (const float*)d_in[2];
    const float* att_src1 = (const float*)d_in[3];
    const float* att_dst1 = (const float*)d_in[4];
    const float* bias1    = (const float*)d_in[5];
    const float* W2       = (const float*)d_in[6];
    const float* att_src2 = (const float*)d_in[7];
    const float* att_dst2 = (const float*)d_in[8];
    const float* bias2    = (const float*)d_in[9];
    float* out = (float*)d_out;

    const int N = in_sizes[0] / IN_C;
    const int E = in_sizes[1] / 2;
    const int NB = (N + SCAN_B - 1) / SCAN_B;

    __half *p_h1h, *p_h2h;
    float *p_out1, *p_as1, *p_ad1, *p_as2, *p_ad2;
    int *p_deg, *p_cur;
    cudaGetSymbolAddress((void**)&p_h1h,  g_h1h);
    cudaGetSymbolAddress((void**)&p_out1, g_out1);
    cudaGetSymbolAddress((void**)&p_h2h,  g_h2h);
    cudaGetSymbolAddress((void**)&p_as1,  g_asrc1);
    cudaGetSymbolAddress((void**)&p_ad1,  g_adst1);
    cudaGetSymbolAddress((void**)&p_as2,  g_asrc2);
    cudaGetSymbolAddress((void**)&p_ad2,  g_adst2);
    cudaGetSymbolAddress((void**)&p_deg,  g_deg);
    cudaGetSymbolAddress((void**)&p_cur,  g_cur);

    const int T = 256;

    // ---- CSR build ----
    ifill_kernel<<<(N + T - 1) / T, T>>>(p_deg, N, 0);
    ifill_kernel<<<(N + T - 1) / T, T>>>(p_cur, N, 0);
    hist_kernel<<<(E + T - 1) / T, T>>>(ei, E);
    scan1_kernel<<<NB, SCAN_B>>>(N);
    scan2_kernel<<<1, SCAN_B>>>(NB);
    scan3_kernel<<<(N + T - 1) / T, T>>>(N);
    scatter_kernel<<<(E + T - 1) / T, T>>>(ei, E);

    // ---- layer 1 ----
    {
        dim3 grid(H1C / 64, (N + 127) / 128);
        gemm_tf32_h<<<grid, 256>>>(x, W1, p_h1h, N, H1C, IN_C);
    }
    att_kernel_h<<<(N * HEADS * 32 + T - 1) / T, T>>>(p_h1h, att_src1, att_dst1,
                                                      p_as1, p_ad1, N, HEADS, HID);
    csr_agg1<<<(int)(((size_t)N * 32 + T - 1) / T), T>>>(bias1, N);

    // ---- layer 2 ----
    {
        dim3 grid(OUT_C / 64, (N + 127) / 128);
        gemm_tf32_h<<<grid, 256>>>(p_out1, W2, p_h2h, N, OUT_C, H1C);
    }
    att_kernel_h<<<(N * 32 + T - 1) / T, T>>>(p_h2h, att_src2, att_dst2,
                                              p_as2, p_ad2, N, 1, OUT_C);
    csr_agg2<<<(int)(((size_t)N * 32 + T - 1) / T), T>>>(bias2, out, N);
}